// round 13
// baseline (speedup 1.0000x reference)
#include <cuda_runtime.h>
#include <cuda_fp16.h>
#include <cstdint>

#define KK     9
#define IN_C   32
#define OUT_C  64
#define HWDIM  256
#define NTH    256

// smem: xs 390 rows (3*130) x 64B = 24960 ; ds 3*132 floats = 1584 ; pk 9*192 words = 6912
#define OFF_DS 24960
#define OFF_PK (OFF_DS + 1584)      // 26544
#define SMEM_BYTES 33792            // also covers epilogue obuf 64*132*4
#define OB_PITCH 132

// B fragments (R8 layout): g_wfrag[((p*3+i)*64 + o)*16 + w], w = ks*8 + cl*2 + sub
//   <-> cp = ks*8 + cl + sub*4
__device__ uint32_t g_wfrag[KK * 3 * OUT_C * 16];

__global__ void prep_weights(const float* __restrict__ w0,
                             const float* __restrict__ w1,
                             const float* __restrict__ w2) {
    int idx = blockIdx.x * blockDim.x + threadIdx.x;
    if (idx >= KK * 3 * OUT_C * 16) return;
    int p = idx / 3072;
    int r = idx % 3072;
    int i = r >> 10;
    int o = (r >> 4) & 63;
    int w = r & 15;
    int ks = w >> 3, clw = (w >> 1) & 3, sub = w & 1;
    int cp = ks * 8 + clw + sub * 4;
    const float* wsrc = (i == 0) ? w0 : (i == 1) ? w1 : w2;
    float v0 = wsrc[(o * IN_C + 2 * cp) * KK + p];
    float v1 = wsrc[(o * IN_C + 2 * cp + 1) * KK + p];
    __half2 hh = __halves2half2(__float2half(v0), __float2half(v1));
    g_wfrag[idx] = *(uint32_t*)&hh;
}

__device__ __forceinline__ void mma_f16(float* d, uint32_t a0, uint32_t a1,
                                        uint32_t a2, uint32_t a3,
                                        uint32_t b0, uint32_t b1) {
    asm volatile(
        "mma.sync.aligned.m16n8k16.row.col.f32.f16.f16.f32 "
        "{%0,%1,%2,%3}, {%4,%5,%6,%7}, {%8,%9}, {%0,%1,%2,%3};"
        : "+f"(d[0]), "+f"(d[1]), "+f"(d[2]), "+f"(d[3])
        : "r"(a0), "r"(a1), "r"(a2), "r"(a3), "r"(b0), "r"(b1));
}

__device__ __forceinline__ uint32_t hmul2u(uint32_t a, uint32_t m) {
    __half2 r = __hmul2(*(__half2*)&a, *(__half2*)&m);
    return *(uint32_t*)&r;
}

__global__ void __launch_bounds__(NTH, 4)
conv25d_r4c(const float* __restrict__ x,
            const float* __restrict__ disp,
            const float* __restrict__ fxp,
            const float* __restrict__ blp,
            float* __restrict__ out) {
    __shared__ __align__(16) char smem[SMEM_BYTES];
    float*    ds  = (float*)(smem + OFF_DS);
    uint32_t* pkw = (uint32_t*)(smem + OFF_PK);

    const int tid  = threadIdx.x;
    const int lane = tid & 31;
    const int wrp  = tid >> 5;
    const int g    = lane >> 2;
    const int cl   = lane & 3;
    const int jb   = (wrp & 3) << 5;
    const int obase = (wrp >> 2) << 5;

    const int b   = blockIdx.x;          // 1024 CTAs
    const int n   = b >> 9;
    const int rem = b & 511;
    const int h   = rem >> 1;
    const int wb  = (rem & 1) << 7;

    const float* xb = x + (size_t)n * IN_C * (HWDIM * HWDIM);
    const float* db = disp + (size_t)n * (HWDIM * HWDIM);

    // ---- stage disp rows ----
    for (int e = tid; e < 3 * 130; e += NTH) {
        int di = e / 130, j = e % 130;
        int gy = h + di - 1, gx = wb - 1 + j;
        float v = 0.0f;
        if (gy >= 0 && gy < HWDIM && gx >= 0 && gx < HWDIM) v = db[gy * HWDIM + gx];
        ds[di * 132 + j] = v;
    }

    // ---- stage x (fp16, 64B rows, R8 XOR-swizzled word layout) ----
    // word w(cp) = ((cp>>3)<<3) | ((cp&3)<<1) | ((cp>>2)&1); pos = w ^ ((row>>1&1)<<3)
    for (int t = wrp; t < 6 * 33; t += 8) {
        int plane = t / 33;
        int jb4   = (t % 33) * 4;
        int di = plane >> 1, cph = plane & 1;
        int cp = cph * 8 + g;
        int j  = jb4 + cl;
        if (j < 130) {
            int gy = h + di - 1, gx = wb - 1 + j;
            float v0 = 0.0f, v1 = 0.0f;
            if (gy >= 0 && gy < HWDIM && gx >= 0 && gx < HWDIM) {
                v0 = xb[(2 * cp) * (HWDIM * HWDIM) + gy * HWDIM + gx];
                v1 = xb[(2 * cp + 1) * (HWDIM * HWDIM) + gy * HWDIM + gx];
            }
            __half2 hh = __halves2half2(__float2half(v0), __float2half(v1));
            int row = di * 130 + j;
            int w = ((cp >> 3) << 3) | ((cp & 3) << 1) | ((cp >> 2) & 1);
            int pos = w ^ (((row >> 1) & 1) << 3);
            *(uint32_t*)(smem + row * 64 + pos * 4) = *(uint32_t*)&hh;
        }
    }
    __syncthreads();

    // ---- precompute ALL 27 masks (bit-exact fp32); thread-halves split p ----
    {
        const int px = tid & 127;
        const float fxv = fxp[n];
        const float bf  = __fmul_rn(blp[n], fxv);
        const float dC  = ds[132 + 1 + px];
        const bool validC = (dC != 0.0f);
        const float depthC = __fdiv_rn(bf, fminf(fmaxf(validC ? dC : 0.0f, 0.01f), 256.0f));
        const float grv    = __fdiv_rn(__fmul_rn(16.0f, depthC), fxv);
        const float halfv  = __fmul_rn(grv, 0.5f);
        const bool lo = ((px >> 3) & 1) == 0;
        const int widx = ((px >> 4) << 3) | (px & 7);
        const int p0 = (tid < 128) ? 0 : 5;
        const int p1 = (tid < 128) ? 5 : 9;
        for (int p = p0; p < p1; p++) {
            int di = p / 3, dj = p % 3;
            float dp = ds[di * 132 + dj + px];
            const bool valid = (dp != 0.0f) && validC;
            const float depth = __fdiv_rn(bf, fminf(fmaxf(valid ? dp : 0.0f, 0.01f), 256.0f));
            float m[3];
            m[0] = (fabsf(__fsub_rn(depth, __fadd_rn(depthC, grv))) <= halfv) ? 1.0f : 0.0f;
            const float ind = (fabsf(__fsub_rn(depth, depthC)) <= halfv) ? 1.0f : 0.0f;
            m[1] = valid ? ind : 1.0f;
            m[2] = (fabsf(__fsub_rn(depth, __fsub_rn(depthC, grv))) <= halfv) ? 1.0f : 0.0f;
#pragma unroll
            for (int i = 0; i < 3; i++) {
                float pm = __shfl_xor_sync(0xffffffffu, m[i], 8);
                if (lo) {
                    __half2 hh = __halves2half2(__float2half(m[i]), __float2half(pm));
                    pkw[p * 192 + i * 64 + widx] = *(uint32_t*)&hh;
                }
            }
        }
    }
    __syncthreads();

    // ---- barrier-free main loop (M32 x N32 per warp, ks-split for low regs) ----
    float acc[2][4][4];
#pragma unroll
    for (int mt = 0; mt < 2; mt++)
#pragma unroll
        for (int n8 = 0; n8 < 4; n8++)
#pragma unroll
            for (int q = 0; q < 4; q++) acc[mt][n8][q] = 0.0f;

#pragma unroll 1
    for (int p = 0; p < KK; p++) {
        const int di = p / 3, dj = p % 3;

        uint32_t pw[3];
        uint32_t pw2[3];
        bool sk[3];
#pragma unroll
        for (int i = 0; i < 3; i++) {
            pw[i]  = pkw[p * 192 + i * 64 + (jb >> 5) * 16 + g];
            pw2[i] = pkw[p * 192 + i * 64 + (jb >> 5) * 16 + 8 + g];
            sk[i] = !__any_sync(0xffffffffu, (pw[i] | pw2[i]) != 0u);
        }
        if (sk[0] && sk[1] && sk[2]) continue;

        const int rowb = di * 130 + dj + jb;

#pragma unroll
        for (int ks = 0; ks < 2; ks++) {
            // A fragments for this k-half: 4 x LDS.64 (conflict-free XOR layout)
            const int pbase = ks * 8 + cl * 2;
            int r;
            r = rowb + g;
            uint2 aL0 = *(const uint2*)(smem + r * 64 + (pbase ^ (((r >> 1) & 1) << 3)) * 4);
            r = rowb + g + 8;
            uint2 aH0 = *(const uint2*)(smem + r * 64 + (pbase ^ (((r >> 1) & 1) << 3)) * 4);
            r = rowb + g + 16;
            uint2 aL1 = *(const uint2*)(smem + r * 64 + (pbase ^ (((r >> 1) & 1) << 3)) * 4);
            r = rowb + g + 24;
            uint2 aH1 = *(const uint2*)(smem + r * 64 + (pbase ^ (((r >> 1) & 1) << 3)) * 4);

#pragma unroll
            for (int i = 0; i < 3; i++) {
                if (sk[i]) continue;
                const uint32_t* wf = g_wfrag + ((size_t)(p * 3 + i) * 64 + obase) * 16
                                   + ks * 8 + cl * 2;
#pragma unroll
                for (int mt = 0; mt < 2; mt++) {
                    uint32_t pv = mt ? pw2[i] : pw[i];
                    __half2 pp = *(__half2*)&pv;
                    __half2 l2 = __half2half2(__low2half(pp));
                    __half2 h2 = __half2half2(__high2half(pp));
                    const uint32_t ml = *(uint32_t*)&l2, mh = *(uint32_t*)&h2;
                    const uint2 aLv = mt ? aL1 : aL0;
                    const uint2 aHv = mt ? aH1 : aH0;
                    uint32_t a0 = hmul2u(aLv.x, ml);
                    uint32_t a1 = hmul2u(aHv.x, mh);
                    uint32_t a2 = hmul2u(aLv.y, ml);
                    uint32_t a3 = hmul2u(aHv.y, mh);
#pragma unroll
                    for (int n8 = 0; n8 < 4; n8++) {
                        uint2 bv = *(const uint2*)(wf + (n8 * 8 + g) * 16);
                        mma_f16(acc[mt][n8], a0, a1, a2, a3, bv.x, bv.y);
                    }
                }
            }
        }
    }

    // ---- epilogue: acc -> smem transpose -> coalesced float4 stores ----
    __syncthreads();
    float* obuf = (float*)smem;   // [o][j], pitch 132
#pragma unroll
    for (int mt = 0; mt < 2; mt++) {
#pragma unroll
        for (int n8 = 0; n8 < 4; n8++) {
            int o = obase + n8 * 8 + cl * 2;
            int j = jb + mt * 16 + g;
            obuf[o * OB_PITCH + j]           = acc[mt][n8][0];
            obuf[(o + 1) * OB_PITCH + j]     = acc[mt][n8][1];
            obuf[o * OB_PITCH + j + 8]       = acc[mt][n8][2];
            obuf[(o + 1) * OB_PITCH + j + 8] = acc[mt][n8][3];
        }
    }
    __syncthreads();
#pragma unroll
    for (int it = 0; it < 8; it++) {
        int e  = tid + it * NTH;
        int o  = e >> 5;
        int j4 = e & 31;
        float4 v = *(const float4*)&obuf[o * OB_PITCH + j4 * 4];
        *(float4*)&out[((size_t)(n * OUT_C + o)) * (HWDIM * HWDIM)
                       + h * HWDIM + wb + j4 * 4] = v;
    }
}

extern "C" void kernel_launch(void* const* d_in, const int* in_sizes, int n_in,
                              void* d_out, int out_size) {
    const float* x    = (const float*)d_in[0];
    const float* disp = (const float*)d_in[1];
    const float* fx   = (const float*)d_in[2];
    const float* bl   = (const float*)d_in[3];
    const float* w0   = (const float*)d_in[4];
    const float* w1   = (const float*)d_in[5];
    const float* w2   = (const float*)d_in[6];
    float* out = (float*)d_out;

    prep_weights<<<(KK * 3 * OUT_C * 16 + 255) / 256, 256>>>(w0, w1, w2);
    conv25d_r4c<<<1024, NTH>>>(x, disp, fx, bl, out);
}

// round 14
// speedup vs baseline: 1.1101x; 1.1101x over previous
#include <cuda_runtime.h>
#include <cuda_fp16.h>
#include <cstdint>

#define KK     9
#define IN_C   32
#define OUT_C  64
#define HWDIM  256
#define NTH    256

// smem: xs 390 rows (3*130) x 64B = 24960 ; ds 3*132 floats = 1584 ; pk 9*192 words = 6912
#define OFF_DS 24960
#define OFF_PK (OFF_DS + 1584)      // 26544
#define SMEM_BYTES 33792            // also covers epilogue obuf 64*132*4
#define OB_PITCH 132

// B fragments (R8 layout): g_wfrag[((p*3+i)*64 + o)*16 + w], w = ks*8 + cl*2 + sub
//   <-> cp = ks*8 + cl + sub*4
__device__ uint32_t g_wfrag[KK * 3 * OUT_C * 16];

__global__ void prep_weights(const float* __restrict__ w0,
                             const float* __restrict__ w1,
                             const float* __restrict__ w2) {
    int idx = blockIdx.x * blockDim.x + threadIdx.x;
    if (idx >= KK * 3 * OUT_C * 16) return;
    int p = idx / 3072;
    int r = idx % 3072;
    int i = r >> 10;
    int o = (r >> 4) & 63;
    int w = r & 15;
    int ks = w >> 3, clw = (w >> 1) & 3, sub = w & 1;
    int cp = ks * 8 + clw + sub * 4;
    const float* wsrc = (i == 0) ? w0 : (i == 1) ? w1 : w2;
    float v0 = wsrc[(o * IN_C + 2 * cp) * KK + p];
    float v1 = wsrc[(o * IN_C + 2 * cp + 1) * KK + p];
    __half2 hh = __halves2half2(__float2half(v0), __float2half(v1));
    g_wfrag[idx] = *(uint32_t*)&hh;
}

__device__ __forceinline__ void mma_f16(float* d, uint32_t a0, uint32_t a1,
                                        uint32_t a2, uint32_t a3,
                                        uint32_t b0, uint32_t b1) {
    asm volatile(
        "mma.sync.aligned.m16n8k16.row.col.f32.f16.f16.f32 "
        "{%0,%1,%2,%3}, {%4,%5,%6,%7}, {%8,%9}, {%0,%1,%2,%3};"
        : "+f"(d[0]), "+f"(d[1]), "+f"(d[2]), "+f"(d[3])
        : "r"(a0), "r"(a1), "r"(a2), "r"(a3), "r"(b0), "r"(b1));
}

__device__ __forceinline__ uint32_t hmul2u(uint32_t a, uint32_t m) {
    __half2 r = __hmul2(*(__half2*)&a, *(__half2*)&m);
    return *(uint32_t*)&r;
}

__global__ void __launch_bounds__(NTH, 3)
conv25d_pf(const float* __restrict__ x,
           const float* __restrict__ disp,
           const float* __restrict__ fxp,
           const float* __restrict__ blp,
           float* __restrict__ out) {
    __shared__ __align__(16) char smem[SMEM_BYTES];
    float*    ds  = (float*)(smem + OFF_DS);
    uint32_t* pkw = (uint32_t*)(smem + OFF_PK);

    const int tid  = threadIdx.x;
    const int lane = tid & 31;
    const int wrp  = tid >> 5;
    const int g    = lane >> 2;
    const int cl   = lane & 3;
    const int jb   = (wrp & 3) << 5;
    const int obase = (wrp >> 2) << 5;

    const int b   = blockIdx.x;          // 1024 CTAs
    const int n   = b >> 9;
    const int rem = b & 511;
    const int h   = rem >> 1;
    const int wb  = (rem & 1) << 7;

    const float* xb = x + (size_t)n * IN_C * (HWDIM * HWDIM);
    const float* db = disp + (size_t)n * (HWDIM * HWDIM);

    // ---- stage disp rows (streaming loads — don't pollute L1D) ----
    for (int e = tid; e < 3 * 130; e += NTH) {
        int di = e / 130, j = e % 130;
        int gy = h + di - 1, gx = wb - 1 + j;
        float v = 0.0f;
        if (gy >= 0 && gy < HWDIM && gx >= 0 && gx < HWDIM) v = __ldcs(&db[gy * HWDIM + gx]);
        ds[di * 132 + j] = v;
    }

    // ---- stage x (fp16, 64B rows, XOR-swizzled word layout; streaming loads) ----
    // word w(cp) = ((cp>>3)<<3) | ((cp&3)<<1) | ((cp>>2)&1); pos = w ^ ((row>>1&1)<<3)
    for (int t = wrp; t < 6 * 33; t += 8) {
        int plane = t / 33;
        int jb4   = (t % 33) * 4;
        int di = plane >> 1, cph = plane & 1;
        int cp = cph * 8 + g;
        int j  = jb4 + cl;
        if (j < 130) {
            int gy = h + di - 1, gx = wb - 1 + j;
            float v0 = 0.0f, v1 = 0.0f;
            if (gy >= 0 && gy < HWDIM && gx >= 0 && gx < HWDIM) {
                v0 = __ldcs(&xb[(2 * cp) * (HWDIM * HWDIM) + gy * HWDIM + gx]);
                v1 = __ldcs(&xb[(2 * cp + 1) * (HWDIM * HWDIM) + gy * HWDIM + gx]);
            }
            __half2 hh = __halves2half2(__float2half(v0), __float2half(v1));
            int row = di * 130 + j;
            int w = ((cp >> 3) << 3) | ((cp & 3) << 1) | ((cp >> 2) & 1);
            int pos = w ^ (((row >> 1) & 1) << 3);
            *(uint32_t*)(smem + row * 64 + pos * 4) = *(uint32_t*)&hh;
        }
    }
    __syncthreads();

    // ---- precompute ALL 27 masks (bit-exact fp32); thread-halves split p ----
    {
        const int px = tid & 127;
        const float fxv = fxp[n];
        const float bf  = __fmul_rn(blp[n], fxv);
        const float dC  = ds[132 + 1 + px];
        const bool validC = (dC != 0.0f);
        const float depthC = __fdiv_rn(bf, fminf(fmaxf(validC ? dC : 0.0f, 0.01f), 256.0f));
        const float grv    = __fdiv_rn(__fmul_rn(16.0f, depthC), fxv);
        const float halfv  = __fmul_rn(grv, 0.5f);
        const bool lo = ((px >> 3) & 1) == 0;
        const int widx = ((px >> 4) << 3) | (px & 7);
        const int p0 = (tid < 128) ? 0 : 5;
        const int p1 = (tid < 128) ? 5 : 9;
        for (int p = p0; p < p1; p++) {
            int di = p / 3, dj = p % 3;
            float dp = ds[di * 132 + dj + px];
            const bool valid = (dp != 0.0f) && validC;
            const float depth = __fdiv_rn(bf, fminf(fmaxf(valid ? dp : 0.0f, 0.01f), 256.0f));
            float m[3];
            m[0] = (fabsf(__fsub_rn(depth, __fadd_rn(depthC, grv))) <= halfv) ? 1.0f : 0.0f;
            const float ind = (fabsf(__fsub_rn(depth, depthC)) <= halfv) ? 1.0f : 0.0f;
            m[1] = valid ? ind : 1.0f;
            m[2] = (fabsf(__fsub_rn(depth, __fsub_rn(depthC, grv))) <= halfv) ? 1.0f : 0.0f;
#pragma unroll
            for (int i = 0; i < 3; i++) {
                float pm = __shfl_xor_sync(0xffffffffu, m[i], 8);
                if (lo) {
                    __half2 hh = __halves2half2(__float2half(m[i]), __float2half(pm));
                    pkw[p * 192 + i * 64 + widx] = *(uint32_t*)&hh;
                }
            }
        }
    }
    __syncthreads();

    // ---- barrier-free main loop (M32 x N32 per warp) ----
    float acc[2][4][4];
#pragma unroll
    for (int mt = 0; mt < 2; mt++)
#pragma unroll
        for (int n8 = 0; n8 < 4; n8++)
#pragma unroll
            for (int q = 0; q < 4; q++) acc[mt][n8][q] = 0.0f;

#pragma unroll 1
    for (int p = 0; p < KK; p++) {
        const int di = p / 3, dj = p % 3;

        uint32_t pw[3], pw2[3];
        bool sk[3];
#pragma unroll
        for (int i = 0; i < 3; i++) {
            pw[i]  = pkw[p * 192 + i * 64 + (jb >> 5) * 16 + g];
            pw2[i] = pkw[p * 192 + i * 64 + (jb >> 5) * 16 + 8 + g];
            sk[i] = !__any_sync(0xffffffffu, (pw[i] | pw2[i]) != 0u);
        }
        if (sk[0] && sk[1] && sk[2]) continue;

        // A fragments, both k-halves, 8 x LDS.64 (conflict-free XOR layout)
        const int rowb = di * 130 + dj + jb;
        uint2 Af[2][4];   // [ks][row-slot: g, g+8, g+16, g+24]
#pragma unroll
        for (int rr = 0; rr < 4; rr++) {
            int r = rowb + rr * 8 + g;
            int x8 = ((r >> 1) & 1) << 3;
#pragma unroll
            for (int ks = 0; ks < 2; ks++) {
                int pos = (ks * 8 + cl * 2) ^ x8;
                Af[ks][rr] = *(const uint2*)(smem + r * 64 + pos * 4);
            }
        }

#pragma unroll
        for (int i = 0; i < 3; i++) {
            if (sk[i]) continue;
            // B fragments, both k-halves batched: 8 x LDG.64 (MLP 8)
            const uint32_t* wf = g_wfrag + ((size_t)(p * 3 + i) * 64 + obase) * 16;
            uint2 bv[2][4];
#pragma unroll
            for (int ks = 0; ks < 2; ks++)
#pragma unroll
                for (int n8 = 0; n8 < 4; n8++)
                    bv[ks][n8] = __ldg((const uint2*)(wf + (n8 * 8 + g) * 16 + ks * 8 + cl * 2));

#pragma unroll
            for (int mt = 0; mt < 2; mt++) {
                uint32_t pv = mt ? pw2[i] : pw[i];
                __half2 pp = *(__half2*)&pv;
                __half2 l2 = __half2half2(__low2half(pp));
                __half2 h2 = __half2half2(__high2half(pp));
                const uint32_t ml = *(uint32_t*)&l2, mh = *(uint32_t*)&h2;
#pragma unroll
                for (int ks = 0; ks < 2; ks++) {
                    uint32_t a0 = hmul2u(Af[ks][mt * 2].x, ml);
                    uint32_t a1 = hmul2u(Af[ks][mt * 2 + 1].x, mh);
                    uint32_t a2 = hmul2u(Af[ks][mt * 2].y, ml);
                    uint32_t a3 = hmul2u(Af[ks][mt * 2 + 1].y, mh);
#pragma unroll
                    for (int n8 = 0; n8 < 4; n8++)
                        mma_f16(acc[mt][n8], a0, a1, a2, a3, bv[ks][n8].x, bv[ks][n8].y);
                }
            }
        }
    }

    // ---- epilogue: acc -> smem transpose -> coalesced float4 streaming stores ----
    __syncthreads();
    float* obuf = (float*)smem;   // [o][j], pitch 132
#pragma unroll
    for (int mt = 0; mt < 2; mt++) {
#pragma unroll
        for (int n8 = 0; n8 < 4; n8++) {
            int o = obase + n8 * 8 + cl * 2;
            int j = jb + mt * 16 + g;
            obuf[o * OB_PITCH + j]           = acc[mt][n8][0];
            obuf[(o + 1) * OB_PITCH + j]     = acc[mt][n8][1];
            obuf[o * OB_PITCH + j + 8]       = acc[mt][n8][2];
            obuf[(o + 1) * OB_PITCH + j + 8] = acc[mt][n8][3];
        }
    }
    __syncthreads();
#pragma unroll
    for (int it = 0; it < 8; it++) {
        int e  = tid + it * NTH;
        int o  = e >> 5;
        int j4 = e & 31;
        float4 v = *(const float4*)&obuf[o * OB_PITCH + j4 * 4];
        __stcs((float4*)&out[((size_t)(n * OUT_C + o)) * (HWDIM * HWDIM)
                             + h * HWDIM + wb + j4 * 4], v);
    }
}

extern "C" void kernel_launch(void* const* d_in, const int* in_sizes, int n_in,
                              void* d_out, int out_size) {
    const float* x    = (const float*)d_in[0];
    const float* disp = (const float*)d_in[1];
    const float* fx   = (const float*)d_in[2];
    const float* bl   = (const float*)d_in[3];
    const float* w0   = (const float*)d_in[4];
    const float* w1   = (const float*)d_in[5];
    const float* w2   = (const float*)d_in[6];
    float* out = (float*)d_out;

    prep_weights<<<(KK * 3 * OUT_C * 16 + 255) / 256, 256>>>(w0, w1, w2);
    conv25d_pf<<<1024, NTH>>>(x, disp, fx, bl, out);
}

// round 15
// speedup vs baseline: 1.4025x; 1.2635x over previous
#include <cuda_runtime.h>
#include <cuda_fp16.h>
#include <cstdint>

#define KK     9
#define IN_C   32
#define OUT_C  64
#define HWDIM  256
#define NTH    256

// smem: xs 3*132 rows x 64B = 25344 ; ds 3*132 floats = 1584 ; pk 9*192 words = 6912
#define OFF_DS 25344
#define OFF_PK (OFF_DS + 1584)      // 26928
#define SMEM_BYTES 33840            // also covers epilogue obuf 64*132*4 = 33792
#define OB_PITCH 132

// B fragments (R8 layout): g_wfrag[((p*3+i)*64 + o)*16 + w], w = ks*8 + cl*2 + sub
__device__ uint32_t g_wfrag[KK * 3 * OUT_C * 16];
// pre-transposed/swizzled fp16 x with zero border: g_xh[((n*258+gy1)*258+gx1)*16 + word]
__device__ uint32_t g_xh[2 * 258 * 258 * 16];

__global__ void prep_weights(const float* __restrict__ w0,
                             const float* __restrict__ w1,
                             const float* __restrict__ w2) {
    int idx = blockIdx.x * blockDim.x + threadIdx.x;
    if (idx >= KK * 3 * OUT_C * 16) return;
    int p = idx / 3072;
    int r = idx % 3072;
    int i = r >> 10;
    int o = (r >> 4) & 63;
    int w = r & 15;
    int ks = w >> 3, clw = (w >> 1) & 3, sub = w & 1;
    int cp = ks * 8 + clw + sub * 4;
    const float* wsrc = (i == 0) ? w0 : (i == 1) ? w1 : w2;
    float v0 = wsrc[(o * IN_C + 2 * cp) * KK + p];
    float v1 = wsrc[(o * IN_C + 2 * cp + 1) * KK + p];
    __half2 hh = __halves2half2(__float2half(v0), __float2half(v1));
    g_wfrag[idx] = *(uint32_t*)&hh;
}

// One-time x transpose+fp16+swizzle. Word layout matches main kernel's smem rows:
// w(cp) = ((cp>>3)<<3)|((cp&3)<<1)|((cp>>2)&1), XORed by bit1(gx1)<<3.
__global__ void prep_x(const float* __restrict__ x) {
    int t = blockIdx.x * blockDim.x + threadIdx.x;
    if (t >= 2 * 258 * 258) return;
    int n   = t / (258 * 258);
    int rem = t % (258 * 258);
    int gy1 = rem / 258, gx1 = rem % 258;
    uint32_t ww[16];
    if (gy1 >= 1 && gy1 <= 256 && gx1 >= 1 && gx1 <= 256) {
        const float* xb = x + (size_t)n * IN_C * 65536 + (gy1 - 1) * 256 + (gx1 - 1);
        int swz = ((gx1 >> 1) & 1) << 3;
#pragma unroll
        for (int cp = 0; cp < 16; cp++) {
            float v0 = xb[(2 * cp) * 65536];
            float v1 = xb[(2 * cp + 1) * 65536];
            __half2 hh = __halves2half2(__float2half(v0), __float2half(v1));
            int w = ((cp >> 3) << 3) | ((cp & 3) << 1) | ((cp >> 2) & 1);
            ww[w ^ swz] = *(uint32_t*)&hh;
        }
    } else {
#pragma unroll
        for (int w = 0; w < 16; w++) ww[w] = 0u;
    }
    uint4* dst = (uint4*)(g_xh + (size_t)t * 16);
#pragma unroll
    for (int q = 0; q < 4; q++)
        dst[q] = make_uint4(ww[q * 4], ww[q * 4 + 1], ww[q * 4 + 2], ww[q * 4 + 3]);
}

__device__ __forceinline__ void mma_f16(float* d, uint32_t a0, uint32_t a1,
                                        uint32_t a2, uint32_t a3,
                                        uint32_t b0, uint32_t b1) {
    asm volatile(
        "mma.sync.aligned.m16n8k16.row.col.f32.f16.f16.f32 "
        "{%0,%1,%2,%3}, {%4,%5,%6,%7}, {%8,%9}, {%0,%1,%2,%3};"
        : "+f"(d[0]), "+f"(d[1]), "+f"(d[2]), "+f"(d[3])
        : "r"(a0), "r"(a1), "r"(a2), "r"(a3), "r"(b0), "r"(b1));
}

__device__ __forceinline__ uint32_t hmul2u(uint32_t a, uint32_t m) {
    __half2 r = __hmul2(*(__half2*)&a, *(__half2*)&m);
    return *(uint32_t*)&r;
}

__global__ void __launch_bounds__(NTH, 3)
conv25d_cp(const float* __restrict__ x,
           const float* __restrict__ disp,
           const float* __restrict__ fxp,
           const float* __restrict__ blp,
           float* __restrict__ out) {
    __shared__ __align__(16) char smem[SMEM_BYTES];
    float*    ds  = (float*)(smem + OFF_DS);
    uint32_t* pkw = (uint32_t*)(smem + OFF_PK);

    uint32_t smem_u32;
    asm("{ .reg .u64 t; cvta.to.shared.u64 t, %1; cvt.u32.u64 %0, t; }"
        : "=r"(smem_u32) : "l"(smem));

    const int tid  = threadIdx.x;
    const int lane = tid & 31;
    const int wrp  = tid >> 5;
    const int g    = lane >> 2;
    const int cl   = lane & 3;
    const int jb   = (wrp & 3) << 5;
    const int obase = (wrp >> 2) << 5;

    const int b   = blockIdx.x;          // 1024 CTAs
    const int n   = b >> 9;
    const int rem = b & 511;
    const int h   = rem >> 1;
    const int wb  = (rem & 1) << 7;

    const float* db = disp + (size_t)n * (HWDIM * HWDIM);

    // ---- async stage x rows: 3 x 130 x 64B contiguous copies from g_xh ----
    {
        const char* xsrc = (const char*)(g_xh + ((size_t)(n * 258 + h) * 258 + wb) * 16);
        for (int e = tid; e < 1560; e += NTH) {
            int di = e / 520, c = e % 520;
            uint32_t dsm = smem_u32 + di * (132 * 64) + c * 16;
            const char* src = xsrc + di * (258 * 64) + c * 16;
            asm volatile("cp.async.cg.shared.global [%0], [%1], 16;"
                         :: "r"(dsm), "l"(src) : "memory");
        }
        asm volatile("cp.async.commit_group;" ::: "memory");
    }

    // ---- stage disp rows (overlapped with the async x copies) ----
    for (int e = tid; e < 3 * 130; e += NTH) {
        int di = e / 130, j = e % 130;
        int gy = h + di - 1, gx = wb - 1 + j;
        float v = 0.0f;
        if (gy >= 0 && gy < HWDIM && gx >= 0 && gx < HWDIM) v = db[gy * HWDIM + gx];
        ds[di * 132 + j] = v;
    }
    __syncthreads();

    // ---- precompute ALL 27 masks (bit-exact fp32); thread-halves split p ----
    {
        const int px = tid & 127;
        const float fxv = fxp[n];
        const float bf  = __fmul_rn(blp[n], fxv);
        const float dC  = ds[132 + 1 + px];
        const bool validC = (dC != 0.0f);
        const float depthC = __fdiv_rn(bf, fminf(fmaxf(validC ? dC : 0.0f, 0.01f), 256.0f));
        const float grv    = __fdiv_rn(__fmul_rn(16.0f, depthC), fxv);
        const float halfv  = __fmul_rn(grv, 0.5f);
        const bool lo = ((px >> 3) & 1) == 0;
        const int widx = ((px >> 4) << 3) | (px & 7);
        const int p0 = (tid < 128) ? 0 : 5;
        const int p1 = (tid < 128) ? 5 : 9;
        for (int p = p0; p < p1; p++) {
            int di = p / 3, dj = p % 3;
            float dp = ds[di * 132 + dj + px];
            const bool valid = (dp != 0.0f) && validC;
            const float depth = __fdiv_rn(bf, fminf(fmaxf(valid ? dp : 0.0f, 0.01f), 256.0f));
            float m[3];
            m[0] = (fabsf(__fsub_rn(depth, __fadd_rn(depthC, grv))) <= halfv) ? 1.0f : 0.0f;
            const float ind = (fabsf(__fsub_rn(depth, depthC)) <= halfv) ? 1.0f : 0.0f;
            m[1] = valid ? ind : 1.0f;
            m[2] = (fabsf(__fsub_rn(depth, __fsub_rn(depthC, grv))) <= halfv) ? 1.0f : 0.0f;
#pragma unroll
            for (int i = 0; i < 3; i++) {
                float pm = __shfl_xor_sync(0xffffffffu, m[i], 8);
                if (lo) {
                    __half2 hh = __halves2half2(__float2half(m[i]), __float2half(pm));
                    pkw[p * 192 + i * 64 + widx] = *(uint32_t*)&hh;
                }
            }
        }
    }
    asm volatile("cp.async.wait_group 0;" ::: "memory");
    __syncthreads();

    // ---- barrier-free main loop (M32 x N32 per warp), masks double-buffered ----
    float acc[2][4][4];
#pragma unroll
    for (int mt = 0; mt < 2; mt++)
#pragma unroll
        for (int n8 = 0; n8 < 4; n8++)
#pragma unroll
            for (int q = 0; q < 4; q++) acc[mt][n8][q] = 0.0f;

    const int pkbase = (jb >> 5) * 16 + g;
    uint32_t cw[3], cx[3];
#pragma unroll
    for (int i = 0; i < 3; i++) {
        cw[i] = pkw[i * 64 + pkbase];
        cx[i] = pkw[i * 64 + pkbase + 8];
    }

#pragma unroll 1
    for (int p = 0; p < KK; p++) {
        // prefetch next p's mask words (ready long before next loop head)
        const int pn = (p < 8) ? p + 1 : 8;
        uint32_t nw[3], nx[3];
#pragma unroll
        for (int i = 0; i < 3; i++) {
            nw[i] = pkw[pn * 192 + i * 64 + pkbase];
            nx[i] = pkw[pn * 192 + i * 64 + pkbase + 8];
        }

        bool sk[3];
#pragma unroll
        for (int i = 0; i < 3; i++)
            sk[i] = !__any_sync(0xffffffffu, (cw[i] | cx[i]) != 0u);

        if (!(sk[0] && sk[1] && sk[2])) {
            const int di = p / 3, dj = p % 3;
            const int rowb = di * 132 + dj + jb;
            const int x8 = (((rowb + g) >> 1) & 1) << 3;   // shared by all 4 rr (rr*8 % 4 == 0)
            const char* xrow = smem + (rowb + g) * 64;

#pragma unroll
            for (int ks = 0; ks < 2; ks++) {
                const int po = ((ks * 8 + cl * 2) ^ x8) * 4;
                uint2 aL0 = *(const uint2*)(xrow + po);
                uint2 aH0 = *(const uint2*)(xrow + 8 * 64 + po);
                uint2 aL1 = *(const uint2*)(xrow + 16 * 64 + po);
                uint2 aH1 = *(const uint2*)(xrow + 24 * 64 + po);

#pragma unroll
                for (int i = 0; i < 3; i++) {
                    if (sk[i]) continue;
                    const uint32_t* wf = g_wfrag + ((size_t)(p * 3 + i) * 64 + obase) * 16
                                       + ks * 8 + cl * 2;
#pragma unroll
                    for (int mt = 0; mt < 2; mt++) {
                        const uint32_t pv = mt ? cx[i] : cw[i];
                        const uint32_t ml = __byte_perm(pv, pv, 0x1010);
                        const uint32_t mh = __byte_perm(pv, pv, 0x3232);
                        const uint2 aLv = mt ? aL1 : aL0;
                        const uint2 aHv = mt ? aH1 : aH0;
                        uint32_t a0 = hmul2u(aLv.x, ml);
                        uint32_t a1 = hmul2u(aHv.x, mh);
                        uint32_t a2 = hmul2u(aLv.y, ml);
                        uint32_t a3 = hmul2u(aHv.y, mh);
#pragma unroll
                        for (int n8 = 0; n8 < 4; n8++) {
                            uint2 bv = *(const uint2*)(wf + (n8 * 8 + g) * 16);
                            mma_f16(acc[mt][n8], a0, a1, a2, a3, bv.x, bv.y);
                        }
                    }
                }
            }
        }
#pragma unroll
        for (int i = 0; i < 3; i++) { cw[i] = nw[i]; cx[i] = nx[i]; }
    }

    // ---- epilogue: acc -> smem transpose -> coalesced float4 stores ----
    __syncthreads();
    float* obuf = (float*)smem;   // [o][j], pitch 132
#pragma unroll
    for (int mt = 0; mt < 2; mt++) {
#pragma unroll
        for (int n8 = 0; n8 < 4; n8++) {
            int o = obase + n8 * 8 + cl * 2;
            int j = jb + mt * 16 + g;
            obuf[o * OB_PITCH + j]           = acc[mt][n8][0];
            obuf[(o + 1) * OB_PITCH + j]     = acc[mt][n8][1];
            obuf[o * OB_PITCH + j + 8]       = acc[mt][n8][2];
            obuf[(o + 1) * OB_PITCH + j + 8] = acc[mt][n8][3];
        }
    }
    __syncthreads();
#pragma unroll
    for (int it = 0; it < 8; it++) {
        int e  = tid + it * NTH;
        int o  = e >> 5;
        int j4 = e & 31;
        float4 v = *(const float4*)&obuf[o * OB_PITCH + j4 * 4];
        *(float4*)&out[((size_t)(n * OUT_C + o)) * (HWDIM * HWDIM)
                       + h * HWDIM + wb + j4 * 4] = v;
    }
}

extern "C" void kernel_launch(void* const* d_in, const int* in_sizes, int n_in,
                              void* d_out, int out_size) {
    const float* x    = (const float*)d_in[0];
    const float* disp = (const float*)d_in[1];
    const float* fx   = (const float*)d_in[2];
    const float* bl   = (const float*)d_in[3];
    const float* w0   = (const float*)d_in[4];
    const float* w1   = (const float*)d_in[5];
    const float* w2   = (const float*)d_in[6];
    float* out = (float*)d_out;

    prep_weights<<<(KK * 3 * OUT_C * 16 + 255) / 256, 256>>>(w0, w1, w2);
    prep_x<<<(2 * 258 * 258 + 255) / 256, 256>>>(x);
    conv25d_cp<<<1024, NTH>>>(x, disp, fx, bl, out);
}

// round 16
// speedup vs baseline: 1.4671x; 1.0461x over previous
#include <cuda_runtime.h>
#include <cuda_fp16.h>
#include <cstdint>

#define KK     9
#define IN_C   32
#define OUT_C  64
#define HWDIM  256
#define NTH    256

// smem: xs 3*132 rows x 64B = 25344 ; ds 3*132 floats = 1584 ; pk 9*192 words = 6912
#define OFF_DS 25344
#define OFF_PK (OFF_DS + 1584)      // 26928
#define SMEM_BYTES 33840            // also covers epilogue obuf 64*132*4 = 33792
#define OB_PITCH 132

#define NXITEMS (2 * 258 * 258)     // 133128
#define NWITEMS (KK * 3 * OUT_C * 16)  // 27648

// B fragments (R8 layout): g_wfrag[((p*3+i)*64 + o)*16 + w], w = ks*8 + cl*2 + sub
__device__ uint32_t g_wfrag[NWITEMS];
// pre-transposed/swizzled fp16 x with zero border: g_xh[((n*258+gy1)*258+gx1)*16 + word]
__device__ uint32_t g_xh[(size_t)NXITEMS * 16];

// Fused prep: items [0, NXITEMS) = x transpose/convert/swizzle, then weights.
__global__ void prep_all(const float* __restrict__ x,
                         const float* __restrict__ w0,
                         const float* __restrict__ w1,
                         const float* __restrict__ w2) {
    int t = blockIdx.x * blockDim.x + threadIdx.x;
    if (t < NXITEMS) {
        int n   = t / (258 * 258);
        int rem = t % (258 * 258);
        int gy1 = rem / 258, gx1 = rem % 258;
        uint32_t ww[16];
        if (gy1 >= 1 && gy1 <= 256 && gx1 >= 1 && gx1 <= 256) {
            const float* xb = x + (size_t)n * IN_C * 65536 + (gy1 - 1) * 256 + (gx1 - 1);
            int swz = ((gx1 >> 1) & 1) << 3;
#pragma unroll
            for (int cp = 0; cp < 16; cp++) {
                float v0 = xb[(2 * cp) * 65536];
                float v1 = xb[(2 * cp + 1) * 65536];
                __half2 hh = __halves2half2(__float2half(v0), __float2half(v1));
                int w = ((cp >> 3) << 3) | ((cp & 3) << 1) | ((cp >> 2) & 1);
                ww[w ^ swz] = *(uint32_t*)&hh;
            }
        } else {
#pragma unroll
            for (int w = 0; w < 16; w++) ww[w] = 0u;
        }
        uint4* dst = (uint4*)(g_xh + (size_t)t * 16);
#pragma unroll
        for (int q = 0; q < 4; q++)
            dst[q] = make_uint4(ww[q * 4], ww[q * 4 + 1], ww[q * 4 + 2], ww[q * 4 + 3]);
    } else {
        int idx = t - NXITEMS;
        if (idx < NWITEMS) {
            int p = idx / 3072;
            int r = idx % 3072;
            int i = r >> 10;
            int o = (r >> 4) & 63;
            int w = r & 15;
            int ks = w >> 3, clw = (w >> 1) & 3, sub = w & 1;
            int cp = ks * 8 + clw + sub * 4;
            const float* wsrc = (i == 0) ? w0 : (i == 1) ? w1 : w2;
            float v0 = wsrc[(o * IN_C + 2 * cp) * KK + p];
            float v1 = wsrc[(o * IN_C + 2 * cp + 1) * KK + p];
            __half2 hh = __halves2half2(__float2half(v0), __float2half(v1));
            g_wfrag[idx] = *(uint32_t*)&hh;
        }
    }
}

__device__ __forceinline__ void mma_f16(float* d, uint32_t a0, uint32_t a1,
                                        uint32_t a2, uint32_t a3,
                                        uint32_t b0, uint32_t b1) {
    asm volatile(
        "mma.sync.aligned.m16n8k16.row.col.f32.f16.f16.f32 "
        "{%0,%1,%2,%3}, {%4,%5,%6,%7}, {%8,%9}, {%0,%1,%2,%3};"
        : "+f"(d[0]), "+f"(d[1]), "+f"(d[2]), "+f"(d[3])
        : "r"(a0), "r"(a1), "r"(a2), "r"(a3), "r"(b0), "r"(b1));
}

__device__ __forceinline__ uint32_t hmul2u(uint32_t a, uint32_t m) {
    __half2 r = __hmul2(*(__half2*)&a, *(__half2*)&m);
    return *(uint32_t*)&r;
}

__global__ void __launch_bounds__(NTH, 3)
conv25d_f(const float* __restrict__ x,
          const float* __restrict__ disp,
          const float* __restrict__ fxp,
          const float* __restrict__ blp,
          float* __restrict__ out) {
    __shared__ __align__(16) char smem[SMEM_BYTES];
    float*    ds  = (float*)(smem + OFF_DS);
    uint32_t* pkw = (uint32_t*)(smem + OFF_PK);

    uint32_t smem_u32;
    asm("{ .reg .u64 t; cvta.to.shared.u64 t, %1; cvt.u32.u64 %0, t; }"
        : "=r"(smem_u32) : "l"(smem));

    const int tid  = threadIdx.x;
    const int lane = tid & 31;
    const int wrp  = tid >> 5;
    const int g    = lane >> 2;
    const int cl   = lane & 3;
    const int jb   = (wrp & 3) << 5;
    const int obase = (wrp >> 2) << 5;

    const int b   = blockIdx.x;          // 1024 CTAs
    const int n   = b >> 9;
    const int rem = b & 511;
    const int h   = rem >> 1;
    const int wb  = (rem & 1) << 7;

    const float* db = disp + (size_t)n * (HWDIM * HWDIM);

    // ---- async stage x rows: 3 x 130 x 64B contiguous copies from g_xh ----
    {
        const char* xsrc = (const char*)(g_xh + ((size_t)(n * 258 + h) * 258 + wb) * 16);
        for (int e = tid; e < 1560; e += NTH) {
            int di = e / 520, c = e % 520;
            uint32_t dsm = smem_u32 + di * (132 * 64) + c * 16;
            const char* src = xsrc + di * (258 * 64) + c * 16;
            asm volatile("cp.async.cg.shared.global [%0], [%1], 16;"
                         :: "r"(dsm), "l"(src) : "memory");
        }
        asm volatile("cp.async.commit_group;" ::: "memory");
    }

    // ---- stage disp rows (overlapped with the async x copies) ----
    for (int e = tid; e < 3 * 130; e += NTH) {
        int di = e / 130, j = e % 130;
        int gy = h + di - 1, gx = wb - 1 + j;
        float v = 0.0f;
        if (gy >= 0 && gy < HWDIM && gx >= 0 && gx < HWDIM) v = db[gy * HWDIM + gx];
        ds[di * 132 + j] = v;
    }
    __syncthreads();

    // ---- precompute ALL 27 masks (bit-exact fp32); thread-halves split p ----
    {
        const int px = tid & 127;
        const float fxv = fxp[n];
        const float bf  = __fmul_rn(blp[n], fxv);
        const float dC  = ds[132 + 1 + px];
        const bool validC = (dC != 0.0f);
        const float depthC = __fdiv_rn(bf, fminf(fmaxf(validC ? dC : 0.0f, 0.01f), 256.0f));
        const float grv    = __fdiv_rn(__fmul_rn(16.0f, depthC), fxv);
        const float halfv  = __fmul_rn(grv, 0.5f);
        const bool lo = ((px >> 3) & 1) == 0;
        const int widx = ((px >> 4) << 3) | (px & 7);
        const int p0 = (tid < 128) ? 0 : 5;
        const int p1 = (tid < 128) ? 5 : 9;
        for (int p = p0; p < p1; p++) {
            int di = p / 3, dj = p % 3;
            float dp = ds[di * 132 + dj + px];
            const bool valid = (dp != 0.0f) && validC;
            const float depth = __fdiv_rn(bf, fminf(fmaxf(valid ? dp : 0.0f, 0.01f), 256.0f));
            float m[3];
            m[0] = (fabsf(__fsub_rn(depth, __fadd_rn(depthC, grv))) <= halfv) ? 1.0f : 0.0f;
            const float ind = (fabsf(__fsub_rn(depth, depthC)) <= halfv) ? 1.0f : 0.0f;
            m[1] = valid ? ind : 1.0f;
            m[2] = (fabsf(__fsub_rn(depth, __fsub_rn(depthC, grv))) <= halfv) ? 1.0f : 0.0f;
#pragma unroll
            for (int i = 0; i < 3; i++) {
                float pm = __shfl_xor_sync(0xffffffffu, m[i], 8);
                if (lo) {
                    __half2 hh = __halves2half2(__float2half(m[i]), __float2half(pm));
                    pkw[p * 192 + i * 64 + widx] = *(uint32_t*)&hh;
                }
            }
        }
    }
    asm volatile("cp.async.wait_group 0;" ::: "memory");
    __syncthreads();

    // ---- barrier-free main loop (M32 x N32 per warp), masks double-buffered ----
    float acc[2][4][4];
#pragma unroll
    for (int mt = 0; mt < 2; mt++)
#pragma unroll
        for (int n8 = 0; n8 < 4; n8++)
#pragma unroll
            for (int q = 0; q < 4; q++) acc[mt][n8][q] = 0.0f;

    const int pkbase = (jb >> 5) * 16 + g;
    uint32_t cw[3], cx[3];
#pragma unroll
    for (int i = 0; i < 3; i++) {
        cw[i] = pkw[i * 64 + pkbase];
        cx[i] = pkw[i * 64 + pkbase + 8];
    }

#pragma unroll 1
    for (int p = 0; p < KK; p++) {
        // prefetch next p's mask words (ready long before next loop head)
        const int pn = (p < 8) ? p + 1 : 8;
        uint32_t nw[3], nx[3];
#pragma unroll
        for (int i = 0; i < 3; i++) {
            nw[i] = pkw[pn * 192 + i * 64 + pkbase];
            nx[i] = pkw[pn * 192 + i * 64 + pkbase + 8];
        }

        bool sk[3];
#pragma unroll
        for (int i = 0; i < 3; i++)
            sk[i] = !__any_sync(0xffffffffu, (cw[i] | cx[i]) != 0u);

        if (!(sk[0] && sk[1] && sk[2])) {
            const int di = p / 3, dj = p % 3;
            const int rowb = di * 132 + dj + jb;
            const int x8 = (((rowb + g) >> 1) & 1) << 3;   // shared by all 4 rr (rr*8 % 4 == 0)
            const char* xrow = smem + (rowb + g) * 64;

#pragma unroll
            for (int ks = 0; ks < 2; ks++) {
                const int po = ((ks * 8 + cl * 2) ^ x8) * 4;
                uint2 aL0 = *(const uint2*)(xrow + po);
                uint2 aH0 = *(const uint2*)(xrow + 8 * 64 + po);
                uint2 aL1 = *(const uint2*)(xrow + 16 * 64 + po);
                uint2 aH1 = *(const uint2*)(xrow + 24 * 64 + po);

#pragma unroll
                for (int i = 0; i < 3; i++) {
                    if (sk[i]) continue;
                    const uint32_t* wf = g_wfrag + ((size_t)(p * 3 + i) * 64 + obase) * 16
                                       + ks * 8 + cl * 2;
#pragma unroll
                    for (int mt = 0; mt < 2; mt++) {
                        const uint32_t pv = mt ? cx[i] : cw[i];
                        const uint32_t ml = __byte_perm(pv, pv, 0x1010);
                        const uint32_t mh = __byte_perm(pv, pv, 0x3232);
                        const uint2 aLv = mt ? aL1 : aL0;
                        const uint2 aHv = mt ? aH1 : aH0;
                        uint32_t a0 = hmul2u(aLv.x, ml);
                        uint32_t a1 = hmul2u(aHv.x, mh);
                        uint32_t a2 = hmul2u(aLv.y, ml);
                        uint32_t a3 = hmul2u(aHv.y, mh);
#pragma unroll
                        for (int n8 = 0; n8 < 4; n8++) {
                            uint2 bv = *(const uint2*)(wf + (n8 * 8 + g) * 16);
                            mma_f16(acc[mt][n8], a0, a1, a2, a3, bv.x, bv.y);
                        }
                    }
                }
            }
        }
#pragma unroll
        for (int i = 0; i < 3; i++) { cw[i] = nw[i]; cx[i] = nx[i]; }
    }

    // ---- epilogue: acc -> smem transpose -> coalesced float4 stores ----
    __syncthreads();
    float* obuf = (float*)smem;   // [o][j], pitch 132
#pragma unroll
    for (int mt = 0; mt < 2; mt++) {
#pragma unroll
        for (int n8 = 0; n8 < 4; n8++) {
            int o = obase + n8 * 8 + cl * 2;
            int j = jb + mt * 16 + g;
            obuf[o * OB_PITCH + j]           = acc[mt][n8][0];
            obuf[(o + 1) * OB_PITCH + j]     = acc[mt][n8][1];
            obuf[o * OB_PITCH + j + 8]       = acc[mt][n8][2];
            obuf[(o + 1) * OB_PITCH + j + 8] = acc[mt][n8][3];
        }
    }
    __syncthreads();
#pragma unroll
    for (int it = 0; it < 8; it++) {
        int e  = tid + it * NTH;
        int o  = e >> 5;
        int j4 = e & 31;
        float4 v = *(const float4*)&obuf[o * OB_PITCH + j4 * 4];
        *(float4*)&out[((size_t)(n * OUT_C + o)) * (HWDIM * HWDIM)
                       + h * HWDIM + wb + j4 * 4] = v;
    }
}

extern "C" void kernel_launch(void* const* d_in, const int* in_sizes, int n_in,
                              void* d_out, int out_size) {
    const float* x    = (const float*)d_in[0];
    const float* disp = (const float*)d_in[1];
    const float* fx   = (const float*)d_in[2];
    const float* bl   = (const float*)d_in[3];
    const float* w0   = (const float*)d_in[4];
    const float* w1   = (const float*)d_in[5];
    const float* w2   = (const float*)d_in[6];
    float* out = (float*)d_out;

    prep_all<<<(NXITEMS + NWITEMS + 255) / 256, 256>>>(x, w0, w1, w2);
    conv25d_f<<<1024, NTH>>>(x, disp, fx, bl, out);
}